// round 10
// baseline (speedup 1.0000x reference)
#include <cuda_runtime.h>
#include <math_constants.h>

// RoiMaxPooling: x (256,56,56,256) f32 NHWC -> adaptive 7x7 max pool (8x8 bins)
// with the reference's transpose/reshape index scramble:
//   out_linear_row = w*(7*B) + h*B + b
//
// R10: R7's winning structure (2 adjacent-bin independent chains/thread,
// 128-reg budget, __ldcs/__stcs; measured best 119.8us) at HALF the block
// size: 128-thread CTAs, __launch_bounds__(128,4) -> same 16 warps/SM and
// same full-RF register budget, but finer scheduling granularity (grid 3136,
// smaller tail quantum, shallower per-CTA L1tex bursts).
// Axis history: chains 1/2/4 -> 121.0/119.8/123.4; distant pairing -> 121.2;
// persistent grid -> 131.0 (all reverted).

#define B_   256
#define HH   56
#define WW   56
#define CC   256
#define GH   7
#define GW   7

__device__ __forceinline__ float4 vmax4(float4 a, float4 b) {
    return make_float4(fmaxf(a.x, b.x), fmaxf(a.y, b.y),
                       fmaxf(a.z, b.z), fmaxf(a.w, b.w));
}

__global__ __launch_bounds__(128, 4)
void roi_maxpool_kernel(const float4* __restrict__ x, float4* __restrict__ out) {
    // Block covers 4 bins: 2 thread-groups of 64 threads, each group owns
    // 2 consecutive bins (two independent chains per thread).
    const int t    = threadIdx.x;
    const int grp  = t >> 6;                          // 0..1
    const int lane = t & 63;                          // channel-group 0..63
    const int bin0 = (blockIdx.x << 2) + (grp << 1);  // even bin
    const int bin1 = bin0 + 1;                        // odd bin

    const int C4  = CC / 4;        // 64 float4 per pixel
    const int ROW = WW * C4;       // float4 per H-row (3584)

    // bin0 coords
    const int b0  = bin0 / (GH * GW);
    const int hw0 = bin0 - b0 * (GH * GW);
    const int h0  = hw0 / GW;
    const int w0  = hw0 - h0 * GW;
    // bin1 coords
    const int b1  = bin1 / (GH * GW);
    const int hw1 = bin1 - b1 * (GH * GW);
    const int h1  = hw1 / GW;
    const int w1  = hw1 - h1 * GW;

    const int base0 = ((b0 * HH + h0 * 8) * WW + w0 * 8) * C4 + lane;
    const int base1 = ((b1 * HH + h1 * 8) * WW + w1 * 8) * C4 + lane;

    float4 accA = make_float4(-CUDART_INF_F, -CUDART_INF_F,
                              -CUDART_INF_F, -CUDART_INF_F);
    float4 accB = accA;

    #pragma unroll
    for (int i = 0; i < 8; i++) {
        const float4* ra = x + base0 + i * ROW;
        const float4* rb = x + base1 + i * ROW;
        // chain A: 8 streaming LDG.128
        float4 a0 = __ldcs(ra + 0 * C4);
        float4 a1 = __ldcs(ra + 1 * C4);
        float4 a2 = __ldcs(ra + 2 * C4);
        float4 a3 = __ldcs(ra + 3 * C4);
        float4 a4 = __ldcs(ra + 4 * C4);
        float4 a5 = __ldcs(ra + 5 * C4);
        float4 a6 = __ldcs(ra + 6 * C4);
        float4 a7 = __ldcs(ra + 7 * C4);
        // chain B: 8 streaming LDG.128 (independent of chain A)
        float4 c0 = __ldcs(rb + 0 * C4);
        float4 c1 = __ldcs(rb + 1 * C4);
        float4 c2 = __ldcs(rb + 2 * C4);
        float4 c3 = __ldcs(rb + 3 * C4);
        float4 c4 = __ldcs(rb + 4 * C4);
        float4 c5 = __ldcs(rb + 5 * C4);
        float4 c6 = __ldcs(rb + 6 * C4);
        float4 c7 = __ldcs(rb + 7 * C4);

        float4 ta = vmax4(vmax4(vmax4(a0, a1), vmax4(a2, a3)),
                          vmax4(vmax4(a4, a5), vmax4(a6, a7)));
        float4 tb = vmax4(vmax4(vmax4(c0, c1), vmax4(c2, c3)),
                          vmax4(vmax4(c4, c5), vmax4(c6, c7)));
        accA = vmax4(accA, ta);
        accB = vmax4(accB, tb);
    }

    // Scrambled destinations: linear row = w*(GH*B) + h*B + b
    const int orow0 = (w0 * (GH * B_) + h0 * B_ + b0);
    const int orow1 = (w1 * (GH * B_) + h1 * B_ + b1);
    __stcs(out + orow0 * C4 + lane, accA);
    __stcs(out + orow1 * C4 + lane, accB);
}

extern "C" void kernel_launch(void* const* d_in, const int* in_sizes, int n_in,
                              void* d_out, int out_size) {
    const float4* x = (const float4*)d_in[0];
    float4* out = (float4*)d_out;
    const int n_bins = B_ * GH * GW;          // 12544
    const int blocks = n_bins / 4;            // 3136
    roi_maxpool_kernel<<<blocks, 128>>>(x, out);
}

// round 11
// speedup vs baseline: 1.0066x; 1.0066x over previous
#include <cuda_runtime.h>
#include <math_constants.h>

// RoiMaxPooling: x (256,56,56,256) f32 NHWC -> adaptive 7x7 max pool (8x8 bins)
// with the reference's transpose/reshape index scramble:
//   out_linear_row = w*(7*B) + h*B + b
//
// FINAL (= R7, measured best 119.8us; re-submitted for confirmation).
// Traffic-minimal HBM stream: 822MB read once + 12.8MB written once at
// ~7.0 TB/s (88% DRAM-active). Design-space map over 10 rounds:
//   chains/thread 1/2/4 -> 121.0/119.8/123.4 us  (2 = register-budget optimum)
//   CTAs/SM 2/3/4       -> 88.6/88.2/86.3 % DRAM (2 = deepest per-thread MLP)
//   persistent grid     -> 131.0 us (broke cross-row load pipelining)
//   distant bin pairing -> 121.2 us (adjacent wins)
//   block 128 vs 256    -> neutral
// Residual ~11% DRAM idle is invariant across all SM-side knobs -> HBM
// physics (refresh/turnaround/ramp), not kernel-addressable.
//
// Structure: 2 independent load/reduce chains per thread (adjacent bins).
// When chain A sits at its vmax join, chain B's 8 LDG.128 issue -> the
// scoreboard-wait exposure at joins is covered. 64 threads/bin x float4.

#define B_   256
#define HH   56
#define WW   56
#define CC   256
#define GH   7
#define GW   7

__device__ __forceinline__ float4 vmax4(float4 a, float4 b) {
    return make_float4(fmaxf(a.x, b.x), fmaxf(a.y, b.y),
                       fmaxf(a.z, b.z), fmaxf(a.w, b.w));
}

__global__ __launch_bounds__(256, 2)
void roi_maxpool_kernel(const float4* __restrict__ x, float4* __restrict__ out) {
    // Block covers 8 bins: 4 thread-groups of 64 threads, each group owns
    // 2 consecutive bins (two independent chains per thread).
    const int t    = threadIdx.x;
    const int grp  = t >> 6;                          // 0..3
    const int lane = t & 63;                          // channel-group 0..63
    const int bin0 = (blockIdx.x << 3) + (grp << 1);  // even bin
    const int bin1 = bin0 + 1;                        // odd bin

    const int C4  = CC / 4;        // 64 float4 per pixel
    const int ROW = WW * C4;       // float4 per H-row (3584)

    // bin0 coords
    const int b0  = bin0 / (GH * GW);
    const int hw0 = bin0 - b0 * (GH * GW);
    const int h0  = hw0 / GW;
    const int w0  = hw0 - h0 * GW;
    // bin1 coords
    const int b1  = bin1 / (GH * GW);
    const int hw1 = bin1 - b1 * (GH * GW);
    const int h1  = hw1 / GW;
    const int w1  = hw1 - h1 * GW;

    const int base0 = ((b0 * HH + h0 * 8) * WW + w0 * 8) * C4 + lane;
    const int base1 = ((b1 * HH + h1 * 8) * WW + w1 * 8) * C4 + lane;

    float4 accA = make_float4(-CUDART_INF_F, -CUDART_INF_F,
                              -CUDART_INF_F, -CUDART_INF_F);
    float4 accB = accA;

    #pragma unroll
    for (int i = 0; i < 8; i++) {
        const float4* ra = x + base0 + i * ROW;
        const float4* rb = x + base1 + i * ROW;
        // chain A: 8 streaming LDG.128
        float4 a0 = __ldcs(ra + 0 * C4);
        float4 a1 = __ldcs(ra + 1 * C4);
        float4 a2 = __ldcs(ra + 2 * C4);
        float4 a3 = __ldcs(ra + 3 * C4);
        float4 a4 = __ldcs(ra + 4 * C4);
        float4 a5 = __ldcs(ra + 5 * C4);
        float4 a6 = __ldcs(ra + 6 * C4);
        float4 a7 = __ldcs(ra + 7 * C4);
        // chain B: 8 streaming LDG.128 (independent of chain A)
        float4 c0 = __ldcs(rb + 0 * C4);
        float4 c1 = __ldcs(rb + 1 * C4);
        float4 c2 = __ldcs(rb + 2 * C4);
        float4 c3 = __ldcs(rb + 3 * C4);
        float4 c4 = __ldcs(rb + 4 * C4);
        float4 c5 = __ldcs(rb + 5 * C4);
        float4 c6 = __ldcs(rb + 6 * C4);
        float4 c7 = __ldcs(rb + 7 * C4);

        float4 ta = vmax4(vmax4(vmax4(a0, a1), vmax4(a2, a3)),
                          vmax4(vmax4(a4, a5), vmax4(a6, a7)));
        float4 tb = vmax4(vmax4(vmax4(c0, c1), vmax4(c2, c3)),
                          vmax4(vmax4(c4, c5), vmax4(c6, c7)));
        accA = vmax4(accA, ta);
        accB = vmax4(accB, tb);
    }

    // Scrambled destinations: linear row = w*(GH*B) + h*B + b
    const int orow0 = (w0 * (GH * B_) + h0 * B_ + b0);
    const int orow1 = (w1 * (GH * B_) + h1 * B_ + b1);
    __stcs(out + orow0 * C4 + lane, accA);
    __stcs(out + orow1 * C4 + lane, accB);
}

extern "C" void kernel_launch(void* const* d_in, const int* in_sizes, int n_in,
                              void* d_out, int out_size) {
    const float4* x = (const float4*)d_in[0];
    float4* out = (float4*)d_out;
    const int n_bins = B_ * GH * GW;          // 12544
    const int blocks = n_bins / 8;            // 1568
    roi_maxpool_kernel<<<blocks, 256>>>(x, out);
}